// round 13
// baseline (speedup 1.0000x reference)
#include <cuda_runtime.h>
#include <cstdint>

#define H       64
#define K       256
#define TILE_M  32
#define TPB     256
#define MARGIN  0.75f
#define BFS     144                      // bf16 row stride in bytes
#define FLT_INF 3.402823466e+38f
#define QMAXG   512                      // queue entries per group

// ---- dynamic smem layout (bytes) ----
#define OFF_CBF   0                      // B = bf16(-2c): 256*144 = 36864
#define OFF_XBF   36864                  // X bf16: 32*144 = 4608 -> 41472
#define OFF_XF32  41472                  // 2 groups * 2 bufs * 4096 = 16384 -> 57856
#define OFF_C2    57856                  // ||c||^2 fp32 exact: 256*4 -> 58880
#define OFF_RMIN  58880                  // 32 rows * 4 quarters * 4B = 512
#define OFF_RES   59392                  // packed (d2,k): 32*8 = 256
#define OFF_Q     59648                  // 2 groups * 512 * 4 = 4096
#define OFF_QN    63744                  // 2 counters, 32B apart
#define OFF_OFL   63808                  // 32*4
#define OFF_RCNT  63936                  // 32*4
#define OFF_RK1   64064                  // 32*4
#define SMEM_TOTAL 64192

#define GBAR(g) asm volatile("bar.sync %0, 128;" :: "r"((g) + 1) : "memory")

__device__ __forceinline__ uint32_t smem_u32(const void* p) {
    uint32_t a;
    asm("{ .reg .u64 t; cvta.to.shared.u64 t, %1; cvt.u32.u64 %0, t; }" : "=r"(a) : "l"(p));
    return a;
}

__device__ __forceinline__ uint32_t bf16x2_pack(float lo, float hi) {
    uint32_t r;
    asm("cvt.rn.bf16x2.f32 %0, %1, %2;" : "=r"(r) : "f"(hi), "f"(lo));
    return r;
}

__device__ __forceinline__ void ldsm4(uint32_t* r, uint32_t addr) {
    asm volatile("ldmatrix.sync.aligned.m8n8.x4.shared.b16 {%0,%1,%2,%3}, [%4];"
        : "=r"(r[0]), "=r"(r[1]), "=r"(r[2]), "=r"(r[3]) : "r"(addr));
}

__device__ __forceinline__ void mma_bf16(float* d, const uint32_t* a, const uint32_t* b) {
    asm volatile("mma.sync.aligned.m16n8k16.row.col.f32.bf16.bf16.f32 "
        "{%0,%1,%2,%3}, {%4,%5,%6,%7}, {%8,%9}, {%0,%1,%2,%3};"
        : "+f"(d[0]), "+f"(d[1]), "+f"(d[2]), "+f"(d[3])
        : "r"(a[0]), "r"(a[1]), "r"(a[2]), "r"(a[3]), "r"(b[0]), "r"(b[1]));
}

__device__ __forceinline__ void cp16(uint32_t dst, const void* src) {
    asm volatile("cp.async.cg.shared.global [%0], [%1], 16;" :: "r"(dst), "l"(src));
}

// exact rescore (sequential-h fp32, float4 loads), monotone-packed (d2,k)
__device__ __forceinline__ unsigned long long rescore_pack(const float* __restrict__ xr,
                                                           const float* __restrict__ crow,
                                                           float c2k, int k) {
    float x2 = 0.f, dot = 0.f;
    #pragma unroll
    for (int h4 = 0; h4 < H / 4; ++h4) {
        float4 xv = *(const float4*)(xr + h4 * 4);
        float4 cv = __ldg((const float4*)(crow + h4 * 4));
        x2 = __fadd_rn(x2, __fmul_rn(xv.x, xv.x));
        dot = __fmaf_rn(xv.x, cv.x, dot);
        x2 = __fadd_rn(x2, __fmul_rn(xv.y, xv.y));
        dot = __fmaf_rn(xv.y, cv.y, dot);
        x2 = __fadd_rn(x2, __fmul_rn(xv.z, xv.z));
        dot = __fmaf_rn(xv.z, cv.z, dot);
        x2 = __fadd_rn(x2, __fmul_rn(xv.w, xv.w));
        dot = __fmaf_rn(xv.w, cv.w, dot);
    }
    float d2 = __fmaf_rn(-2.f, dot, __fadd_rn(x2, c2k));
    uint32_t b = __float_as_uint(d2);
    b ^= (b & 0x80000000u) ? 0xFFFFFFFFu : 0x80000000u;    // monotone map
    return ((unsigned long long)b << 32) | (unsigned)k;
}

extern __shared__ char smem_raw[];

__global__ __launch_bounds__(TPB, 3)
void LatentSpaceClustering_46797963657837_kernel(const float* __restrict__ x,
                                                 const float* __restrict__ c,
                                                 float* __restrict__ out,
                                                 int n, int num_tiles) {
    const uint32_t sbase = smem_u32(smem_raw);
    float* c2f  = (float*)(smem_raw + OFF_C2);
    float* rmin = (float*)(smem_raw + OFF_RMIN);
    unsigned long long* res = (unsigned long long*)(smem_raw + OFF_RES);
    int* ofl  = (int*)(smem_raw + OFF_OFL);
    int* rcnt = (int*)(smem_raw + OFF_RCNT);
    int* rk1  = (int*)(smem_raw + OFF_RK1);
    const int tid = threadIdx.x;
    const int lane = tid & 31, w = tid >> 5;
    const int groupID = lane >> 2, tig = lane & 3;
    const int q4 = w & 3, g = w >> 2;               // warp's n-quarter, group id
    const int gtid = tid & 127;                     // 0..127 within group
    const int nb = q4 * 64;                         // n base for this warp

    uint32_t* qp  = (uint32_t*)(smem_raw + OFF_Q) + g * QMAXG;
    int*      qnp = (int*)(smem_raw + OFF_QN + g * 32);

    // ---- stage B = bf16(-2c) (padded rows) ----
    {
        const float4* c4 = (const float4*)c;
        for (int j = tid; j < K * H / 4; j += TPB) {
            float4 v = c4[j];
            int k = j >> 4, h = (j & 15) << 2;
            uint2 p = make_uint2(bf16x2_pack(-2.f * v.x, -2.f * v.y),
                                 bf16x2_pack(-2.f * v.z, -2.f * v.w));
            *(uint2*)(smem_raw + OFF_CBF + k * BFS + h * 2) = p;
        }
    }
    // ---- exact ||c_k||^2 (fp32 sequential, reference-style) ----
    {
        int k = tid;                                // TPB == K
        const float* cr = c + k * H;
        float s = 0.f;
        #pragma unroll 8
        for (int h = 0; h < H; ++h) {
            float v = __ldg(cr + h);
            s = __fadd_rn(s, __fmul_rn(v, v));
        }
        c2f[k] = s;
    }
    __syncthreads();

    const uint32_t xf32g = sbase + OFF_XF32 + g * 8192;   // group fp32 area (2 bufs)

    // ---- first-tile prefetch (group's own 16 rows) ----
    {
        long long gb = (long long)blockIdx.x * TILE_M + g * 16;
        #pragma unroll
        for (int i = 0; i < 2; ++i) {
            int chunk = i * 128 + gtid;             // 256 chunks of 16B
            int row = chunk >> 4, seg = chunk & 15;
            if (gb + row < n)
                cp16(xf32g + row * 256 + seg * 16, x + (gb + row) * H + seg * 4);
        }
        asm volatile("cp.async.commit_group;");
    }

    const uint32_t a_base = sbase + OFF_XBF + (g * 16 + (lane & 15)) * BFS + ((lane >> 4) * 16);
    const uint32_t b_base = sbase + OFF_CBF
        + (nb + (lane & 7) + ((lane >> 4) << 3)) * BFS
        + (((lane >> 3) & 1) * 16);
    const int r0 = g * 16 + groupID, r1 = r0 + 8;   // CTA-tile rows for this thread

    int buf = 0;
    for (int tile = blockIdx.x; tile < num_tiles; tile += gridDim.x) {
        const long long gbase = (long long)tile * TILE_M + g * 16;
        asm volatile("cp.async.wait_group 0;" ::: "memory");
        GBAR(g);

        // ---- convert fp32 -> bf16 (group rows); init group state ----
        const float* xf = (const float*)(smem_raw + OFF_XF32 + g * 8192 + buf * 4096);
        #pragma unroll
        for (int i = 0; i < 2; ++i) {
            int idx = i * 128 + gtid;               // 256 = 16 rows * 16 float4
            int row = idx >> 4, h4 = idx & 15;
            float4 v = ((const float4*)xf)[row * 16 + h4];
            uint2 p = make_uint2(bf16x2_pack(v.x, v.y), bf16x2_pack(v.z, v.w));
            *(uint2*)(smem_raw + OFF_XBF + (g * 16 + row) * BFS + h4 * 8) = p;
        }
        if (gtid < 16) {
            int rg = g * 16 + gtid;
            res[rg] = 0xFFFFFFFFFFFFFFFFull;
            ofl[rg] = 0;
            rcnt[rg] = 0;
        }
        if (gtid == 16) *qnp = 0;
        GBAR(g);

        // ---- prefetch next tile into other buffer ----
        {
            long long nxt = (long long)(tile + gridDim.x) * TILE_M + g * 16;
            if (tile + gridDim.x < num_tiles) {
                #pragma unroll
                for (int i = 0; i < 2; ++i) {
                    int chunk = i * 128 + gtid;
                    int row = chunk >> 4, seg = chunk & 15;
                    if (nxt + row < n)
                        cp16(xf32g + (buf ^ 1) * 4096 + row * 256 + seg * 16,
                             x + (nxt + row) * H + seg * 4);
                }
            }
            asm volatile("cp.async.commit_group;");
        }

        // ---- acc init = c2 (exact); mma with B = -2c => acc = c2 - 2 x.c ----
        float acc[32];
        #pragma unroll
        for (int j = 0; j < 8; ++j) {
            float2 c2v = *(const float2*)(c2f + nb + j * 8 + tig * 2);
            acc[j*4+0] = c2v.x; acc[j*4+1] = c2v.y;
            acc[j*4+2] = c2v.x; acc[j*4+3] = c2v.y;
        }
        uint32_t a[4][4];
        #pragma unroll
        for (int ks = 0; ks < 4; ++ks) ldsm4(a[ks], a_base + ks * 32);

        uint32_t bb[2][4];
        ldsm4(bb[0], b_base);
        #pragma unroll
        for (int it = 0; it < 16; ++it) {           // it = ks*4 + jpair
            int cur = it & 1;
            if (it < 15) {
                int nx = it + 1;
                ldsm4(bb[cur ^ 1], b_base + (nx & 3) * (16 * BFS) + (nx >> 2) * 32);
            }
            int jp = it & 3, ks = it >> 2;
            mma_bf16(acc + (jp * 2) * 4,     a[ks], bb[cur]);
            mma_bf16(acc + (jp * 2 + 1) * 4, a[ks], bb[cur] + 2);
        }

        // ---- per-row partial min (acc already = screening score) ----
        float mn0 = FLT_INF, mn1 = FLT_INF;
        #pragma unroll
        for (int j = 0; j < 8; ++j) {
            mn0 = fminf(mn0, fminf(acc[j*4+0], acc[j*4+1]));
            mn1 = fminf(mn1, fminf(acc[j*4+2], acc[j*4+3]));
        }
        #pragma unroll
        for (int off = 1; off <= 2; off <<= 1) {
            mn0 = fminf(mn0, __shfl_xor_sync(0xffffffffu, mn0, off));
            mn1 = fminf(mn1, __shfl_xor_sync(0xffffffffu, mn1, off));
        }
        if (tig == 0) { rmin[r0 * 4 + q4] = mn0; rmin[r1 * 4 + q4] = mn1; }
        GBAR(g);

        // ---- screen vs combined row threshold; push to group queue ----
        float4 m0 = *(const float4*)(rmin + r0 * 4);
        float4 m1 = *(const float4*)(rmin + r1 * 4);
        const float thr0 = fminf(fminf(m0.x, m0.y), fminf(m0.z, m0.w)) + MARGIN;
        const float thr1 = fminf(fminf(m1.x, m1.y), fminf(m1.z, m1.w)) + MARGIN;
        #pragma unroll
        for (int j = 0; j < 8; ++j) {
            #pragma unroll
            for (int e = 0; e < 2; ++e) {
                int k = nb + j * 8 + tig * 2 + e;
                if (acc[j*4+e] < thr0) {
                    atomicAdd(&rcnt[r0], 1);
                    rk1[r0] = k;
                    int idx = atomicAdd(qnp, 1);
                    if (idx < QMAXG) qp[idx] = ((uint32_t)groupID << 8) | (uint32_t)k;
                    else ofl[r0] = 1;
                }
                if (acc[j*4+2+e] < thr1) {
                    atomicAdd(&rcnt[r1], 1);
                    rk1[r1] = k;
                    int idx = atomicAdd(qnp, 1);
                    if (idx < QMAXG) qp[idx] = ((uint32_t)(groupID + 8) << 8) | (uint32_t)k;
                    else ofl[r1] = 1;
                }
            }
        }
        GBAR(g);

        // ---- single-candidate fast path ----
        if (gtid < 16) {
            int rg = g * 16 + gtid;
            if (rcnt[rg] == 1) res[rg] = (unsigned)rk1[rg];
        }
        // ---- group-parallel exact rescore for multi-candidate rows ----
        {
            int total = *qnp;
            if (total > QMAXG) total = QMAXG;
            for (int i = gtid; i < total; i += 128) {
                uint32_t e = qp[i];
                int rl = e >> 8, k = e & 255;
                int rg = g * 16 + rl;
                if (rcnt[rg] > 1)
                    atomicMin(&res[rg],
                              rescore_pack(xf + rl * H, c + (size_t)k * H, c2f[k], k));
            }
        }
        // overflow fallback (pathological only)
        if (gtid < 16) {
            int rg = g * 16 + gtid;
            if (ofl[rg]) {
                for (int k = 0; k < K; ++k)
                    atomicMin(&res[rg],
                              rescore_pack(xf + gtid * H, c + (size_t)k * H, c2f[k], k));
            }
        }
        GBAR(g);

        // ---- write back (group rows) ----
        if (gtid < 16) {
            long long gg = gbase + gtid;
            if (gg < n) out[gg] = (float)(uint32_t)(res[g * 16 + gtid] & 0xFFFFFFFFull);
        }

        buf ^= 1;
    }
}

extern "C" void kernel_launch(void* const* d_in, const int* in_sizes, int n_in,
                              void* d_out, int out_size) {
    const float* x = (const float*)d_in[0];
    const float* c = (const float*)d_in[1];
    int n = in_sizes[0] / H;
    int num_tiles = (n + TILE_M - 1) / TILE_M;

    int sms = 148;
    cudaDeviceGetAttribute(&sms, cudaDevAttrMultiProcessorCount, 0);

    cudaFuncSetAttribute(LatentSpaceClustering_46797963657837_kernel,
                         cudaFuncAttributeMaxDynamicSharedMemorySize, SMEM_TOTAL);

    int grid = 3 * sms;
    if (grid > num_tiles) grid = num_tiles;
    LatentSpaceClustering_46797963657837_kernel<<<grid, TPB, SMEM_TOTAL>>>(
        x, c, (float*)d_out, n, num_tiles);
}

// round 14
// speedup vs baseline: 1.0835x; 1.0835x over previous
#include <cuda_runtime.h>
#include <cstdint>

#define H       64
#define K       256
#define TILE_M  64
#define TPB     256
#define MARGIN  0.75f
#define BFS     144                      // bf16 row stride in bytes
#define FLT_INF 3.402823466e+38f
#define QMAXG   512                      // queue entries per group

// ---- dynamic smem layout (bytes) ----
#define OFF_CBF   0                      // B = bf16(-2c): 256*144 = 36864
#define OFF_XBF   36864                  // X bf16: 64*144 = 9216 -> 46080
#define OFF_XF32  46080                  // 2 groups * 2 bufs * 8192 = 32768 -> 78848
#define OFF_C2    78848                  // ||c||^2 fp32 exact (pad 1024) -> 79872
#define OFF_RMIN  79872                  // 64 rows * 4 quarters * 4B = 1024 -> 80896
#define OFF_RES   80896                  // packed (d2,k): 64*8 = 512 -> 81408
#define OFF_Q     81408                  // 2 groups * 512 * 4 = 4096 -> 85504
#define OFF_QN    85504                  // 2 counters, 32B apart -> 85568
#define OFF_OFL   85568                  // 64*4 -> 85824
#define OFF_RCNT  85824                  // 64*4 -> 86080
#define OFF_RK1   86080                  // 64*4 -> 86336
#define SMEM_TOTAL 86336

#define GBAR(g) asm volatile("bar.sync %0, 128;" :: "r"((g) + 1) : "memory")

__device__ __forceinline__ uint32_t smem_u32(const void* p) {
    uint32_t a;
    asm("{ .reg .u64 t; cvta.to.shared.u64 t, %1; cvt.u32.u64 %0, t; }" : "=r"(a) : "l"(p));
    return a;
}

__device__ __forceinline__ uint32_t bf16x2_pack(float lo, float hi) {
    uint32_t r;
    asm("cvt.rn.bf16x2.f32 %0, %1, %2;" : "=r"(r) : "f"(hi), "f"(lo));
    return r;
}

__device__ __forceinline__ void ldsm4(uint32_t* r, uint32_t addr) {
    asm volatile("ldmatrix.sync.aligned.m8n8.x4.shared.b16 {%0,%1,%2,%3}, [%4];"
        : "=r"(r[0]), "=r"(r[1]), "=r"(r[2]), "=r"(r[3]) : "r"(addr));
}

__device__ __forceinline__ void mma_bf16(float* d, const uint32_t* a, const uint32_t* b) {
    asm volatile("mma.sync.aligned.m16n8k16.row.col.f32.bf16.bf16.f32 "
        "{%0,%1,%2,%3}, {%4,%5,%6,%7}, {%8,%9}, {%0,%1,%2,%3};"
        : "+f"(d[0]), "+f"(d[1]), "+f"(d[2]), "+f"(d[3])
        : "r"(a[0]), "r"(a[1]), "r"(a[2]), "r"(a[3]), "r"(b[0]), "r"(b[1]));
}

__device__ __forceinline__ void cp16(uint32_t dst, const void* src) {
    asm volatile("cp.async.cg.shared.global [%0], [%1], 16;" :: "r"(dst), "l"(src));
}

// exact rescore (sequential-h fp32, float4 loads), monotone-packed (d2,k)
__device__ __forceinline__ unsigned long long rescore_pack(const float* __restrict__ xr,
                                                           const float* __restrict__ crow,
                                                           float c2k, int k) {
    float x2 = 0.f, dot = 0.f;
    #pragma unroll
    for (int h4 = 0; h4 < H / 4; ++h4) {
        float4 xv = *(const float4*)(xr + h4 * 4);
        float4 cv = __ldg((const float4*)(crow + h4 * 4));
        x2 = __fadd_rn(x2, __fmul_rn(xv.x, xv.x));
        dot = __fmaf_rn(xv.x, cv.x, dot);
        x2 = __fadd_rn(x2, __fmul_rn(xv.y, xv.y));
        dot = __fmaf_rn(xv.y, cv.y, dot);
        x2 = __fadd_rn(x2, __fmul_rn(xv.z, xv.z));
        dot = __fmaf_rn(xv.z, cv.z, dot);
        x2 = __fadd_rn(x2, __fmul_rn(xv.w, xv.w));
        dot = __fmaf_rn(xv.w, cv.w, dot);
    }
    float d2 = __fmaf_rn(-2.f, dot, __fadd_rn(x2, c2k));
    uint32_t b = __float_as_uint(d2);
    b ^= (b & 0x80000000u) ? 0xFFFFFFFFu : 0x80000000u;    // monotone map
    return ((unsigned long long)b << 32) | (unsigned)k;
}

extern __shared__ char smem_raw[];

__global__ __launch_bounds__(TPB, 2)
void LatentSpaceClustering_46797963657837_kernel(const float* __restrict__ x,
                                                 const float* __restrict__ c,
                                                 float* __restrict__ out,
                                                 int n, int num_tiles) {
    const uint32_t sbase = smem_u32(smem_raw);
    float* c2f  = (float*)(smem_raw + OFF_C2);
    float* rmin = (float*)(smem_raw + OFF_RMIN);
    unsigned long long* res = (unsigned long long*)(smem_raw + OFF_RES);
    int* ofl  = (int*)(smem_raw + OFF_OFL);
    int* rcnt = (int*)(smem_raw + OFF_RCNT);
    int* rk1  = (int*)(smem_raw + OFF_RK1);
    const int tid = threadIdx.x;
    const int lane = tid & 31, w = tid >> 5;
    const int groupID = lane >> 2, tig = lane & 3;
    const int q4 = w & 3, g = w >> 2;               // n-quarter, group (m-half)
    const int gtid = tid & 127;                     // 0..127 within group
    const int nb = q4 * 64;                         // n base for this warp

    uint32_t* qp  = (uint32_t*)(smem_raw + OFF_Q) + g * QMAXG;
    int*      qnp = (int*)(smem_raw + OFF_QN + g * 32);

    // ---- stage B = bf16(-2c) (padded rows) ----
    {
        const float4* c4 = (const float4*)c;
        for (int j = tid; j < K * H / 4; j += TPB) {
            float4 v = c4[j];
            int k = j >> 4, h = (j & 15) << 2;
            uint2 p = make_uint2(bf16x2_pack(-2.f * v.x, -2.f * v.y),
                                 bf16x2_pack(-2.f * v.z, -2.f * v.w));
            *(uint2*)(smem_raw + OFF_CBF + k * BFS + h * 2) = p;
        }
    }
    // ---- exact ||c_k||^2 (fp32 sequential, reference-style) ----
    {
        int k = tid;                                // TPB == K
        const float* cr = c + k * H;
        float s = 0.f;
        #pragma unroll 8
        for (int h = 0; h < H; ++h) {
            float v = __ldg(cr + h);
            s = __fadd_rn(s, __fmul_rn(v, v));
        }
        c2f[k] = s;
    }
    __syncthreads();

    const uint32_t xf32g = sbase + OFF_XF32 + g * 16384;  // group fp32 area (2 bufs)

    // ---- first-tile prefetch (group's 32 rows: 512 x 16B chunks) ----
    {
        long long gb = (long long)blockIdx.x * TILE_M + g * 32;
        #pragma unroll
        for (int i = 0; i < 4; ++i) {
            int chunk = i * 128 + gtid;
            int row = chunk >> 4, seg = chunk & 15;
            if (gb + row < n)
                cp16(xf32g + row * 256 + seg * 16, x + (gb + row) * H + seg * 4);
        }
        asm volatile("cp.async.commit_group;");
    }

    const uint32_t a_base = sbase + OFF_XBF + (g * 32 + (lane & 15)) * BFS + ((lane >> 4) * 16);
    const uint32_t b_base = sbase + OFF_CBF
        + (nb + (lane & 7) + ((lane >> 4) << 3)) * BFS
        + (((lane >> 3) & 1) * 16);
    // rows owned by this thread (CTA-tile indices)
    const int rA0 = g * 32 + groupID,      rA1 = rA0 + 8;    // m-tile 0
    const int rB0 = g * 32 + 16 + groupID, rB1 = rB0 + 8;    // m-tile 1

    int buf = 0;
    for (int tile = blockIdx.x; tile < num_tiles; tile += gridDim.x) {
        const long long gbase = (long long)tile * TILE_M + g * 32;
        asm volatile("cp.async.wait_group 0;" ::: "memory");
        GBAR(g);

        // ---- convert fp32 -> bf16 (group rows); init group state ----
        const float* xf = (const float*)(smem_raw + OFF_XF32 + g * 16384 + buf * 8192);
        #pragma unroll
        for (int i = 0; i < 4; ++i) {
            int idx = i * 128 + gtid;               // 512 = 32 rows * 16 float4
            int row = idx >> 4, h4 = idx & 15;
            float4 v = ((const float4*)xf)[row * 16 + h4];
            uint2 p = make_uint2(bf16x2_pack(v.x, v.y), bf16x2_pack(v.z, v.w));
            *(uint2*)(smem_raw + OFF_XBF + (g * 32 + row) * BFS + h4 * 8) = p;
        }
        if (gtid < 32) {
            int rg = g * 32 + gtid;
            res[rg] = 0xFFFFFFFFFFFFFFFFull;
            ofl[rg] = 0;
            rcnt[rg] = 0;
        }
        if (gtid == 32) *qnp = 0;
        GBAR(g);

        // ---- prefetch next tile into other buffer ----
        {
            long long nxt = (long long)(tile + gridDim.x) * TILE_M + g * 32;
            if (tile + gridDim.x < num_tiles) {
                #pragma unroll
                for (int i = 0; i < 4; ++i) {
                    int chunk = i * 128 + gtid;
                    int row = chunk >> 4, seg = chunk & 15;
                    if (nxt + row < n)
                        cp16(xf32g + (buf ^ 1) * 8192 + row * 256 + seg * 16,
                             x + (nxt + row) * H + seg * 4);
                }
            }
            asm volatile("cp.async.commit_group;");
        }

        // ---- acc init = exact c2; B = -2c => acc = c2 - 2 x.c (screen score) ----
        float acc0[32], acc1[32];
        #pragma unroll
        for (int j = 0; j < 8; ++j) {
            float2 c2v = *(const float2*)(c2f + nb + j * 8 + tig * 2);
            acc0[j*4+0] = c2v.x; acc0[j*4+1] = c2v.y;
            acc0[j*4+2] = c2v.x; acc0[j*4+3] = c2v.y;
            acc1[j*4+0] = c2v.x; acc1[j*4+1] = c2v.y;
            acc1[j*4+2] = c2v.x; acc1[j*4+3] = c2v.y;
        }
        uint32_t a0[4][4], a1[4][4];
        #pragma unroll
        for (int ks = 0; ks < 4; ++ks) {
            ldsm4(a0[ks], a_base + ks * 32);
            ldsm4(a1[ks], a_base + 16 * BFS + ks * 32);
        }

        uint32_t bb[2][4];
        ldsm4(bb[0], b_base);
        #pragma unroll
        for (int it = 0; it < 16; ++it) {           // it = ks*4 + jpair
            int cur = it & 1;
            if (it < 15) {
                int nx = it + 1;
                ldsm4(bb[cur ^ 1], b_base + (nx & 3) * (16 * BFS) + (nx >> 2) * 32);
            }
            int jp = it & 3, ks = it >> 2;
            mma_bf16(acc0 + (jp * 2) * 4,     a0[ks], bb[cur]);
            mma_bf16(acc0 + (jp * 2 + 1) * 4, a0[ks], bb[cur] + 2);
            mma_bf16(acc1 + (jp * 2) * 4,     a1[ks], bb[cur]);
            mma_bf16(acc1 + (jp * 2 + 1) * 4, a1[ks], bb[cur] + 2);
        }

        // ---- per-row partial mins (acc already = screening score) ----
        float mA0 = FLT_INF, mA1 = FLT_INF, mB0 = FLT_INF, mB1 = FLT_INF;
        #pragma unroll
        for (int j = 0; j < 8; ++j) {
            mA0 = fminf(mA0, fminf(acc0[j*4+0], acc0[j*4+1]));
            mA1 = fminf(mA1, fminf(acc0[j*4+2], acc0[j*4+3]));
            mB0 = fminf(mB0, fminf(acc1[j*4+0], acc1[j*4+1]));
            mB1 = fminf(mB1, fminf(acc1[j*4+2], acc1[j*4+3]));
        }
        #pragma unroll
        for (int off = 1; off <= 2; off <<= 1) {
            mA0 = fminf(mA0, __shfl_xor_sync(0xffffffffu, mA0, off));
            mA1 = fminf(mA1, __shfl_xor_sync(0xffffffffu, mA1, off));
            mB0 = fminf(mB0, __shfl_xor_sync(0xffffffffu, mB0, off));
            mB1 = fminf(mB1, __shfl_xor_sync(0xffffffffu, mB1, off));
        }
        if (tig == 0) {
            rmin[rA0 * 4 + q4] = mA0; rmin[rA1 * 4 + q4] = mA1;
            rmin[rB0 * 4 + q4] = mB0; rmin[rB1 * 4 + q4] = mB1;
        }
        GBAR(g);

        // ---- screen vs combined row thresholds; push to group queue ----
        float4 v0 = *(const float4*)(rmin + rA0 * 4);
        float4 v1 = *(const float4*)(rmin + rA1 * 4);
        float4 v2 = *(const float4*)(rmin + rB0 * 4);
        float4 v3 = *(const float4*)(rmin + rB1 * 4);
        const float tA0 = fminf(fminf(v0.x, v0.y), fminf(v0.z, v0.w)) + MARGIN;
        const float tA1 = fminf(fminf(v1.x, v1.y), fminf(v1.z, v1.w)) + MARGIN;
        const float tB0 = fminf(fminf(v2.x, v2.y), fminf(v2.z, v2.w)) + MARGIN;
        const float tB1 = fminf(fminf(v3.x, v3.y), fminf(v3.z, v3.w)) + MARGIN;
        #pragma unroll
        for (int j = 0; j < 8; ++j) {
            #pragma unroll
            for (int e = 0; e < 2; ++e) {
                int k = nb + j * 8 + tig * 2 + e;
                if (acc0[j*4+e] < tA0) {
                    atomicAdd(&rcnt[rA0], 1); rk1[rA0] = k;
                    int idx = atomicAdd(qnp, 1);
                    if (idx < QMAXG) qp[idx] = ((uint32_t)groupID << 8) | (uint32_t)k;
                    else ofl[rA0] = 1;
                }
                if (acc0[j*4+2+e] < tA1) {
                    atomicAdd(&rcnt[rA1], 1); rk1[rA1] = k;
                    int idx = atomicAdd(qnp, 1);
                    if (idx < QMAXG) qp[idx] = ((uint32_t)(groupID + 8) << 8) | (uint32_t)k;
                    else ofl[rA1] = 1;
                }
                if (acc1[j*4+e] < tB0) {
                    atomicAdd(&rcnt[rB0], 1); rk1[rB0] = k;
                    int idx = atomicAdd(qnp, 1);
                    if (idx < QMAXG) qp[idx] = ((uint32_t)(groupID + 16) << 8) | (uint32_t)k;
                    else ofl[rB0] = 1;
                }
                if (acc1[j*4+2+e] < tB1) {
                    atomicAdd(&rcnt[rB1], 1); rk1[rB1] = k;
                    int idx = atomicAdd(qnp, 1);
                    if (idx < QMAXG) qp[idx] = ((uint32_t)(groupID + 24) << 8) | (uint32_t)k;
                    else ofl[rB1] = 1;
                }
            }
        }
        GBAR(g);

        // ---- single-candidate fast path ----
        if (gtid < 32) {
            int rg = g * 32 + gtid;
            if (rcnt[rg] == 1) res[rg] = (unsigned)rk1[rg];
        }
        // ---- group-parallel exact rescore for multi-candidate rows ----
        {
            int total = *qnp;
            if (total > QMAXG) total = QMAXG;
            for (int i = gtid; i < total; i += 128) {
                uint32_t e = qp[i];
                int rl = e >> 8, k = e & 255;
                int rg = g * 32 + rl;
                if (rcnt[rg] > 1)
                    atomicMin(&res[rg],
                              rescore_pack(xf + rl * H, c + (size_t)k * H, c2f[k], k));
            }
        }
        // overflow fallback (pathological only)
        if (gtid < 32) {
            int rg = g * 32 + gtid;
            if (ofl[rg]) {
                for (int k = 0; k < K; ++k)
                    atomicMin(&res[rg],
                              rescore_pack(xf + gtid * H, c + (size_t)k * H, c2f[k], k));
            }
        }
        GBAR(g);

        // ---- write back (group rows) ----
        if (gtid < 32) {
            long long gg = gbase + gtid;
            if (gg < n) out[gg] = (float)(uint32_t)(res[g * 32 + gtid] & 0xFFFFFFFFull);
        }

        buf ^= 1;
    }
}

extern "C" void kernel_launch(void* const* d_in, const int* in_sizes, int n_in,
                              void* d_out, int out_size) {
    const float* x = (const float*)d_in[0];
    const float* c = (const float*)d_in[1];
    int n = in_sizes[0] / H;
    int num_tiles = (n + TILE_M - 1) / TILE_M;

    int sms = 148;
    cudaDeviceGetAttribute(&sms, cudaDevAttrMultiProcessorCount, 0);

    cudaFuncSetAttribute(LatentSpaceClustering_46797963657837_kernel,
                         cudaFuncAttributeMaxDynamicSharedMemorySize, SMEM_TOTAL);

    int grid = 2 * sms;
    if (grid > num_tiles) grid = num_tiles;
    LatentSpaceClustering_46797963657837_kernel<<<grid, TPB, SMEM_TOTAL>>>(
        x, c, (float*)d_out, n, num_tiles);
}